// round 1
// baseline (speedup 1.0000x reference)
#include <cuda_runtime.h>
#include <cuda_bf16.h>

// ExponentialMovingAverage: y[n] = w*x[n] + (1-w)*y[n-1], scan over frames axis.
// input:         (16, 8, 256, 2048) f32, frames contiguous
// initial_state: (16, 8, 256) f32
// weight:        (8, 256) f32, clamped to [0,1]
// output:        (16, 8, 256, 2048) f32
//
// One CTA of 256 threads per channel (32768 channels). Each thread owns 8
// contiguous frames. The recurrence is the affine map y -> a*y + b which
// composes associatively: local pass builds per-thread (a,b), a warp-shuffle
// scan + 8-entry cross-warp scan yields each thread's exact incoming state,
// then the 8 elements are replayed from registers and stored vectorized.

#define NFRAMES   2048
#define NTHREADS  256
#define NCHANNELS (16 * 8 * 256)

__global__ __launch_bounds__(NTHREADS)
void ema_scan_kernel(const float* __restrict__ in,
                     const float* __restrict__ init_state,
                     const float* __restrict__ wt,
                     float* __restrict__ out)
{
    const int ch   = blockIdx.x;
    const int t    = threadIdx.x;
    const int lane = t & 31;
    const int warp = t >> 5;

    // weight index = ch % (8*256); clamp to [0,1]
    float w = wt[ch & 2047];
    w = fminf(fmaxf(w, 0.0f), 1.0f);
    const float omw = 1.0f - w;

    // Load this thread's 8 contiguous frames (2 x LDG.128)
    const float4* ip = reinterpret_cast<const float4*>(in + (size_t)ch * NFRAMES) + 2 * t;
    float4 x0 = ip[0];
    float4 x1 = ip[1];
    float xs[8] = {x0.x, x0.y, x0.z, x0.w, x1.x, x1.y, x1.z, x1.w};

    // Local affine composition over the chunk: y_out = a*y_in + b
    float a = 1.0f, b = 0.0f;
    #pragma unroll
    for (int j = 0; j < 8; ++j) {
        b = omw * b + w * xs[j];
        a *= omw;
    }

    // Inclusive warp scan of affine pairs.
    // Compose earlier (pa,pb) then later (ia,ib): a' = pa*ia, b' = ia*pb + ib
    float ia = a, ib = b;
    #pragma unroll
    for (int d = 1; d < 32; d <<= 1) {
        float pa = __shfl_up_sync(0xffffffffu, ia, d);
        float pb = __shfl_up_sync(0xffffffffu, ib, d);
        if (lane >= d) {
            ib = ia * pb + ib;   // uses pre-update ia
            ia = ia * pa;
        }
    }

    __shared__ float sa[8];
    __shared__ float sb[8];
    if (lane == 31) { sa[warp] = ia; sb[warp] = ib; }

    // Exclusive scan within warp (shift by 1; lane 0 = identity)
    float ea = __shfl_up_sync(0xffffffffu, ia, 1);
    float eb = __shfl_up_sync(0xffffffffu, ib, 1);
    if (lane == 0) { ea = 1.0f; eb = 0.0f; }

    __syncthreads();

    // Exclusive prefix over warp aggregates (only 8 entries — do it per-thread)
    float wpa = 1.0f, wpb = 0.0f;
    #pragma unroll
    for (int k = 0; k < 7; ++k) {
        if (k < warp) {
            wpb = sa[k] * wpb + sb[k];
            wpa *= sa[k];
        }
    }

    // Full exclusive transform: warp-prefix (earlier) then in-warp exclusive (later)
    const float afull = wpa * ea;
    const float bfull = ea * wpb + eb;

    // Incoming state for this thread's chunk
    float y = afull * init_state[ch] + bfull;

    // Replay the 8 elements exactly as the reference recurrence
    float4 o0, o1;
    y = w * xs[0] + omw * y; o0.x = y;
    y = w * xs[1] + omw * y; o0.y = y;
    y = w * xs[2] + omw * y; o0.z = y;
    y = w * xs[3] + omw * y; o0.w = y;
    y = w * xs[4] + omw * y; o1.x = y;
    y = w * xs[5] + omw * y; o1.y = y;
    y = w * xs[6] + omw * y; o1.z = y;
    y = w * xs[7] + omw * y; o1.w = y;

    float4* op = reinterpret_cast<float4*>(out + (size_t)ch * NFRAMES) + 2 * t;
    op[0] = o0;
    op[1] = o1;
}

extern "C" void kernel_launch(void* const* d_in, const int* in_sizes, int n_in,
                              void* d_out, int out_size)
{
    const float* input   = (const float*)d_in[0];  // (16,8,256,2048)
    const float* init_st = (const float*)d_in[1];  // (16,8,256)
    const float* weight  = (const float*)d_in[2];  // (8,256)
    float* out = (float*)d_out;

    ema_scan_kernel<<<NCHANNELS, NTHREADS>>>(input, init_st, weight, out);
}

// round 2
// speedup vs baseline: 1.0229x; 1.0229x over previous
#include <cuda_runtime.h>
#include <cuda_bf16.h>

// ExponentialMovingAverage: y[n] = w*x[n] + (1-w)*y[n-1] along frames axis.
// input (16,8,256,2048) f32 contiguous; initial_state (16,8,256); weight (8,256) clamped.
//
// One CTA (256 threads) per channel. INTERLEAVED ownership for perfectly
// coalesced LDG.128/STG.128: thread t owns frames [4t,4t+4) (chunk0) and
// [1024+4t, 1024+4t+4) (chunk1). The recurrence is affine y->a*y+b; we scan
// BOTH chunks' affine pairs simultaneously with warp shuffles + an 8-entry
// cross-warp scan, then chain chunk1 through the block-total of chunk0.

#define NFRAMES   2048
#define NTHREADS  256
#define HALF      (NFRAMES / 2)        // 1024 frames per sweep
#define NCHANNELS (16 * 8 * 256)

__global__ __launch_bounds__(NTHREADS)
void ema_scan_kernel(const float* __restrict__ in,
                     const float* __restrict__ init_state,
                     const float* __restrict__ wt,
                     float* __restrict__ out)
{
    const int ch   = blockIdx.x;
    const int t    = threadIdx.x;
    const int lane = t & 31;
    const int warp = t >> 5;

    float w = wt[ch & 2047];
    w = fminf(fmaxf(w, 0.0f), 1.0f);
    const float omw = 1.0f - w;

    // Two fully-coalesced LDG.128: chunk0 at frames 4t.., chunk1 at 1024+4t..
    const float4* ip = reinterpret_cast<const float4*>(in + (size_t)ch * NFRAMES);
    float4 x0 = ip[t];
    float4 x1 = ip[NTHREADS + t];

    // Local affine composition for each 4-element chunk: y_out = a*y_in + b
    // chunk0:
    float a0, b0;
    {
        float b = w * x0.x;
        b = omw * b + w * x0.y;
        b = omw * b + w * x0.z;
        b = omw * b + w * x0.w;
        float o2 = omw * omw;
        a0 = o2 * o2;
        b0 = b;
    }
    // chunk1:
    float a1, b1;
    {
        float b = w * x1.x;
        b = omw * b + w * x1.y;
        b = omw * b + w * x1.z;
        b = omw * b + w * x1.w;
        a1 = a0;   // same (1-w)^4
        b1 = b;
    }

    // Inclusive warp scan of both affine pairs simultaneously.
    // Compose earlier p then later i: a' = i.a*p.a, b' = i.a*p.b + i.b
    float ia0 = a0, ib0 = b0, ia1 = a1, ib1 = b1;
    #pragma unroll
    for (int d = 1; d < 32; d <<= 1) {
        float pa0 = __shfl_up_sync(0xffffffffu, ia0, d);
        float pb0 = __shfl_up_sync(0xffffffffu, ib0, d);
        float pa1 = __shfl_up_sync(0xffffffffu, ia1, d);
        float pb1 = __shfl_up_sync(0xffffffffu, ib1, d);
        if (lane >= d) {
            ib0 = ia0 * pb0 + ib0;  ia0 = ia0 * pa0;
            ib1 = ia1 * pb1 + ib1;  ia1 = ia1 * pa1;
        }
    }

    __shared__ float sa0[8], sb0[8], sa1[8], sb1[8];
    if (lane == 31) { sa0[warp] = ia0; sb0[warp] = ib0;
                      sa1[warp] = ia1; sb1[warp] = ib1; }

    // In-warp exclusive transforms (shift by 1; lane 0 = identity)
    float ea0 = __shfl_up_sync(0xffffffffu, ia0, 1);
    float eb0 = __shfl_up_sync(0xffffffffu, ib0, 1);
    float ea1 = __shfl_up_sync(0xffffffffu, ia1, 1);
    float eb1 = __shfl_up_sync(0xffffffffu, ib1, 1);
    if (lane == 0) { ea0 = 1.0f; eb0 = 0.0f; ea1 = 1.0f; eb1 = 0.0f; }

    __syncthreads();

    // Cross-warp: exclusive prefixes for this warp (both chunks) and the
    // block-total of chunk0 (needed to seed chunk1's sweep).
    float wpa0 = 1.0f, wpb0 = 0.0f;       // exclusive prefix, chunk0 aggregates
    float wpa1 = 1.0f, wpb1 = 0.0f;       // exclusive prefix, chunk1 aggregates
    float ta0  = 1.0f, tb0  = 0.0f;       // inclusive total of chunk0
    #pragma unroll
    for (int k = 0; k < 8; ++k) {
        float ka0 = sa0[k], kb0 = sb0[k];
        if (k < warp) {
            wpb0 = ka0 * wpb0 + kb0;  wpa0 *= ka0;
            float ka1 = sa1[k];
            wpb1 = ka1 * wpb1 + sb1[k];  wpa1 *= ka1;
        }
        tb0 = ka0 * tb0 + kb0;  ta0 *= ka0;
    }

    // Full exclusive transforms: warp-prefix (earlier) then in-warp exclusive.
    const float A0 = wpa0 * ea0;
    const float B0 = ea0 * wpb0 + eb0;
    const float A1 = wpa1 * ea1;
    const float B1 = ea1 * wpb1 + eb1;

    const float yinit = init_state[ch];
    // Incoming state for chunk0, and for chunk1 (through chunk0 block-total):
    float y0 = A0 * yinit + B0;
    const float ytot0 = ta0 * yinit + tb0;   // state after frame 1023
    float y1 = A1 * ytot0 + B1;

    // Replay both chunks exactly as the reference recurrence.
    float4 o0, o1;
    y0 = w * x0.x + omw * y0; o0.x = y0;
    y0 = w * x0.y + omw * y0; o0.y = y0;
    y0 = w * x0.z + omw * y0; o0.z = y0;
    y0 = w * x0.w + omw * y0; o0.w = y0;

    y1 = w * x1.x + omw * y1; o1.x = y1;
    y1 = w * x1.y + omw * y1; o1.y = y1;
    y1 = w * x1.z + omw * y1; o1.z = y1;
    y1 = w * x1.w + omw * y1; o1.w = y1;

    float4* op = reinterpret_cast<float4*>(out + (size_t)ch * NFRAMES);
    op[t] = o0;
    op[NTHREADS + t] = o1;
}

extern "C" void kernel_launch(void* const* d_in, const int* in_sizes, int n_in,
                              void* d_out, int out_size)
{
    const float* input   = (const float*)d_in[0];
    const float* init_st = (const float*)d_in[1];
    const float* weight  = (const float*)d_in[2];
    float* out = (float*)d_out;

    ema_scan_kernel<<<NCHANNELS, NTHREADS>>>(input, init_st, weight, out);
}